// round 6
// baseline (speedup 1.0000x reference)
#include <cuda_runtime.h>
#include <cuda_bf16.h>
#include <math.h>
#include <stdint.h>

#define TOKENS 2048
#define DM 1024
#define NH 16
#define HD 64

// ---------------- scratch (device globals: no allocs allowed) ----------------
__device__ float g_qraw[TOKENS * DM];
__device__ float g_kraw[TOKENS * DM];
__device__ float g_vraw[TOKENS * DM];
__device__ float g_beta[TOKENS * NH];
__device__ float g_att [TOKENS * DM];

__device__ __nv_bfloat16 g_xhi[TOKENS * DM], g_xlo[TOKENS * DM];
__device__ __nv_bfloat16 g_atthi[TOKENS * DM], g_attlo[TOKENS * DM];
__device__ __nv_bfloat16 g_wqhi[DM * DM], g_wqlo[DM * DM];
__device__ __nv_bfloat16 g_wkhi[DM * DM], g_wklo[DM * DM];
__device__ __nv_bfloat16 g_wvhi[DM * DM], g_wvlo[DM * DM];
__device__ __nv_bfloat16 g_wohi[DM * DM], g_wolo[DM * DM];

// ======================= helpers =======================
__device__ __forceinline__ uint32_t smem_u32(const void* p) {
    uint32_t a;
    asm("{ .reg .u64 t; cvta.to.shared.u64 t, %1; cvt.u32.u64 %0, t; }" : "=r"(a) : "l"(p));
    return a;
}
#define CP_ASYNC16(dst, src) \
    asm volatile("cp.async.cg.shared.global [%0], [%1], 16;" :: "r"(dst), "l"(src) : "memory")
#define CP_ASYNC4(dst, src) \
    asm volatile("cp.async.ca.shared.global [%0], [%1], 4;" :: "r"(dst), "l"(src) : "memory")
#define CP_COMMIT() asm volatile("cp.async.commit_group;" ::: "memory")
#define CP_WAIT(n)  asm volatile("cp.async.wait_group %0;" :: "n"(n) : "memory")
#define SWZ(off) ((off) ^ (((off) >> 3) & 0x70))

__device__ __forceinline__ void ldm4(uint32_t addr, uint32_t* r) {
    asm volatile("ldmatrix.sync.aligned.m8n8.x4.shared.b16 {%0,%1,%2,%3}, [%4];"
                 : "=r"(r[0]), "=r"(r[1]), "=r"(r[2]), "=r"(r[3]) : "r"(addr));
}
__device__ __forceinline__ void mma16816(float* c, const uint32_t* a, const uint32_t* b) {
    asm volatile(
        "mma.sync.aligned.m16n8k16.row.col.f32.bf16.bf16.f32 "
        "{%0,%1,%2,%3}, {%4,%5,%6,%7}, {%8,%9}, {%0,%1,%2,%3};"
        : "+f"(c[0]), "+f"(c[1]), "+f"(c[2]), "+f"(c[3])
        : "r"(a[0]), "r"(a[1]), "r"(a[2]), "r"(a[3]), "r"(b[0]), "r"(b[1]));
}

// ---- packed f32x2 ----
typedef unsigned long long ull;
__device__ __forceinline__ ull pk2(float a, float b) {
    ull r; asm("mov.b64 %0, {%1, %2};" : "=l"(r) : "f"(a), "f"(b)); return r;
}
__device__ __forceinline__ void upk2(ull v, float& a, float& b) {
    asm("mov.b64 {%0, %1}, %2;" : "=f"(a), "=f"(b) : "l"(v));
}
#define FMA2(acc, a, b) \
    asm("fma.rn.f32x2 %0, %1, %2, %0;" : "+l"(acc) : "l"(a), "l"(b))

// ---------------- fp32 -> bf16 hi/lo split (elementwise) ----------------
__global__ __launch_bounds__(256)
void split_kernel(const float* __restrict__ src, __nv_bfloat16* __restrict__ hi,
                  __nv_bfloat16* __restrict__ lo, int n4)
{
    int i = blockIdx.x * blockDim.x + threadIdx.x;
    if (i >= n4) return;
    float4 v = ((const float4*)src)[i];
    __nv_bfloat16 hx = __float2bfloat16(v.x), hy = __float2bfloat16(v.y),
                  hz = __float2bfloat16(v.z), hw = __float2bfloat16(v.w);
    ((ushort4*)hi)[i] = make_ushort4(__bfloat16_as_ushort(hx), __bfloat16_as_ushort(hy),
                                     __bfloat16_as_ushort(hz), __bfloat16_as_ushort(hw));
    __nv_bfloat16 lx = __float2bfloat16(v.x - __bfloat162float(hx));
    __nv_bfloat16 ly = __float2bfloat16(v.y - __bfloat162float(hy));
    __nv_bfloat16 lz = __float2bfloat16(v.z - __bfloat162float(hz));
    __nv_bfloat16 lw = __float2bfloat16(v.w - __bfloat162float(hw));
    ((ushort4*)lo)[i] = make_ushort4(__bfloat16_as_ushort(lx), __bfloat16_as_ushort(ly),
                                     __bfloat16_as_ushort(lz), __bfloat16_as_ushort(lw));
}

// =================== tensor-core GEMM: C[2048,1024] = A[2048,1024] * B[1024,1024]^T ===================
#define STAGE_BYTES 65536
#define GEMM_SMEM (2 * STAGE_BYTES)

__device__ __forceinline__ void stage_load(
    uint32_t sb, int stage, int tid, int m0, int n0, int k0,
    const __nv_bfloat16* __restrict__ Ahi, const __nv_bfloat16* __restrict__ Alo,
    const __nv_bfloat16* __restrict__ Bhi, const __nv_bfloat16* __restrict__ Blo)
{
#pragma unroll
    for (int i = 0; i < 16; i++) {
        const int mi = i >> 2;
        const int cid = ((i & 3) << 8) + tid;
        const int row = cid >> 3;
        const int c16 = cid & 7;
        const __nv_bfloat16* g = (mi == 0) ? Ahi : (mi == 1) ? Alo : (mi == 2) ? Bhi : Blo;
        const int grow = ((mi < 2) ? m0 : n0) + row;
        const void* src = g + (size_t)grow * DM + k0 + c16 * 8;
        uint32_t off = (uint32_t)(row * 128 + c16 * 16);
        uint32_t dst = sb + stage * STAGE_BYTES + mi * 16384 + SWZ(off);
        CP_ASYNC16(dst, src);
    }
    CP_COMMIT();
}

__global__ __launch_bounds__(256, 1)
void gemm_bs(const __nv_bfloat16* __restrict__ Ahi, const __nv_bfloat16* __restrict__ Alo,
             const __nv_bfloat16* __restrict__ Bhi, const __nv_bfloat16* __restrict__ Blo,
             float* __restrict__ C)
{
    extern __shared__ char smem[];
    const uint32_t sb = smem_u32(smem);
    const int tid = threadIdx.x;
    const int wid = tid >> 5;
    const int lane = tid & 31;
    const int m0 = blockIdx.y * 128;
    const int n0 = blockIdx.x * 128;
    const int wm = (wid & 3) * 32;
    const int wn = (wid >> 2) * 64;

    float acc[2][8][4];
#pragma unroll
    for (int mt = 0; mt < 2; mt++)
#pragma unroll
        for (int nt = 0; nt < 8; nt++)
#pragma unroll
            for (int j = 0; j < 4; j++) acc[mt][nt][j] = 0.f;

    stage_load(sb, 0, tid, m0, n0, 0, Ahi, Alo, Bhi, Blo);

    for (int ch = 0; ch < 16; ch++) {
        if (ch < 15) {
            stage_load(sb, (ch + 1) & 1, tid, m0, n0, (ch + 1) * 64, Ahi, Alo, Bhi, Blo);
            CP_WAIT(1);
        } else {
            CP_WAIT(0);
        }
        __syncthreads();

        const uint32_t sA_hi = sb + (ch & 1) * STAGE_BYTES;
        const uint32_t sA_lo = sA_hi + 16384;
        const uint32_t sB_hi = sA_hi + 32768;
        const uint32_t sB_lo = sA_hi + 49152;

#pragma unroll
        for (int kk = 0; kk < 4; kk++) {
            const int kb = kk * 32 + ((lane >> 4) & 1) * 16;

            uint32_t ahi[2][4], alo[2][4];
#pragma unroll
            for (int mt = 0; mt < 2; mt++) {
                uint32_t off = (uint32_t)((wm + mt * 16 + (lane & 15)) * 128 + kb);
                uint32_t so = SWZ(off);
                ldm4(sA_hi + so, ahi[mt]);
                ldm4(sA_lo + so, alo[mt]);
            }

            uint32_t bhi[8][2], blo[8][2];
#pragma unroll
            for (int p = 0; p < 4; p++) {
                uint32_t off = (uint32_t)((wn + p * 16 + (lane & 15)) * 128 + kb);
                uint32_t so = SWZ(off);
                uint32_t t[4];
                ldm4(sB_hi + so, t);
                bhi[2 * p][0] = t[0]; bhi[2 * p + 1][0] = t[1];
                bhi[2 * p][1] = t[2]; bhi[2 * p + 1][1] = t[3];
                ldm4(sB_lo + so, t);
                blo[2 * p][0] = t[0]; blo[2 * p + 1][0] = t[1];
                blo[2 * p][1] = t[2]; blo[2 * p + 1][1] = t[3];
            }

#pragma unroll
            for (int mt = 0; mt < 2; mt++)
#pragma unroll
                for (int nt = 0; nt < 8; nt++) {
                    mma16816(acc[mt][nt], ahi[mt], bhi[nt]);
                    mma16816(acc[mt][nt], ahi[mt], blo[nt]);
                    mma16816(acc[mt][nt], alo[mt], bhi[nt]);
                }
        }
        __syncthreads();
    }

#pragma unroll
    for (int mt = 0; mt < 2; mt++) {
        const int r0 = m0 + wm + mt * 16 + (lane >> 2);
#pragma unroll
        for (int nt = 0; nt < 8; nt++) {
            const int c0 = n0 + wn + nt * 8 + 2 * (lane & 3);
            *(float2*)(C + (size_t)r0 * DM + c0)       = make_float2(acc[mt][nt][0], acc[mt][nt][1]);
            *(float2*)(C + (size_t)(r0 + 8) * DM + c0) = make_float2(acc[mt][nt][2], acc[mt][nt][3]);
        }
    }
}

// ---------------- beta = 2*sigmoid(x @ Wb^T), one warp per head ----------------
__global__ __launch_bounds__(512)
void beta_kernel(const float* __restrict__ x, const float* __restrict__ Wb)
{
    int token = blockIdx.x;
    int w = threadIdx.x >> 5;
    int lane = threadIdx.x & 31;
    const float* xr = x + (size_t)token * DM;
    const float* wr = Wb + (size_t)w * DM;
    float s = 0.f;
    for (int j = lane; j < DM; j += 32) s += xr[j] * wr[j];
#pragma unroll
    for (int o = 16; o; o >>= 1) s += __shfl_xor_sync(0xffffffffu, s, o);
    if (lane == 0) g_beta[token * NH + w] = 2.f / (1.f + __expf(-s));
}

__device__ __forceinline__ float silu(float v) { return v / (1.f + __expf(-v)); }

// ------- silu + per-head L2 normalize for q,k; silu for v (in place) -------
__global__ __launch_bounds__(256)
void act_kernel()
{
    int token = blockIdx.x;
    int tid = threadIdx.x;
    size_t off = (size_t)token * DM + tid * 4;

    float4 q = *(float4*)(g_qraw + off);
    q.x = silu(q.x); q.y = silu(q.y); q.z = silu(q.z); q.w = silu(q.w);
    float ss = q.x * q.x + q.y * q.y + q.z * q.z + q.w * q.w;
#pragma unroll
    for (int o = 8; o; o >>= 1) ss += __shfl_xor_sync(0xffffffffu, ss, o);
    float inv = 1.f / (sqrtf(ss) + 1e-6f);
    q.x *= inv; q.y *= inv; q.z *= inv; q.w *= inv;
    *(float4*)(g_qraw + off) = q;

    float4 k = *(float4*)(g_kraw + off);
    k.x = silu(k.x); k.y = silu(k.y); k.z = silu(k.z); k.w = silu(k.w);
    float sk = k.x * k.x + k.y * k.y + k.z * k.z + k.w * k.w;
#pragma unroll
    for (int o = 8; o; o >>= 1) sk += __shfl_xor_sync(0xffffffffu, sk, o);
    float invk = 1.f / (sqrtf(sk) + 1e-6f);
    k.x *= invk; k.y *= invk; k.z *= invk; k.w *= invk;
    *(float4*)(g_kraw + off) = k;

    float4 v = *(float4*)(g_vraw + off);
    v.x = silu(v.x); v.y = silu(v.y); v.z = silu(v.z); v.w = silu(v.w);
    *(float4*)(g_vraw + off) = v;
}

// ---------------- sequential delta-rule scan: f32x2 + 1 barrier/step ----------------
// 256 threads. Thread (w, g, p): w=warp(0..7), g=group(0..7), p=part(0..3).
// rc = w*8+g : this thread's OWN row AND column index of the 64x64 state M.
//   mcol2[j] = packed (M[p*16+2j][rc], M[p*16+2j+1][rc])  -> out = M^T q, col update
//   mrow2[j] = packed (M[rc][p*16+2j], M[rc][p*16+2j+1])  -> retrieved = M k, row update
// Partial dots reduced over p via 2x shfl_xor. bd[rc] computed in-warp (row==col),
// so only the row update needs the full bd vector -> ONE CTA barrier per step.
#define SBLK 8
#define NBLK (1024 / SBLK)

__global__ __launch_bounds__(256, 1)
void scan_kernel()
{
    const int pair = blockIdx.x;
    const int b = pair >> 4, h = pair & 15;
    const int tid = threadIdx.x;
    const int lane = tid & 31;
    const int p = lane & 3;
    const int rc = (tid >> 5) * 8 + (lane >> 2);   // own row/col 0..63
    const int pb = p * 16;                          // contraction base

    __shared__ __align__(16) float ring[2][3][SBLK][64];
    __shared__ __align__(16) float ring_b[2][SBLK];
    __shared__ __align__(16) float bd_sh[2][64];

    ull mcol2[8], mrow2[8];
#pragma unroll
    for (int j = 0; j < 8; j++) { mcol2[j] = 0ull; mrow2[j] = 0ull; }

    const size_t hb = (size_t)b * 1024 * DM + h * HD;
    const float* qp = g_qraw + hb;
    const float* kp = g_kraw + hb;
    const float* vp = g_vraw + hb;
    const float* bp = g_beta + (size_t)b * 1024 * NH + h;
    float* op = g_att + hb;

    auto prefetch = [&](int blk, int buf) {
        const int t0 = blk * SBLK;
#pragma unroll
        for (int i = 0; i < 2; i++) {
            int idx = tid + i * 256;
            if (idx < 384) {
                int arr = idx >> 7;
                int rem = idx & 127;
                int s = rem >> 4;
                int c = (rem & 15) * 4;
                const float* src = (arr == 0 ? qp : arr == 1 ? kp : vp)
                                   + (size_t)(t0 + s) * DM + c;
                CP_ASYNC16(smem_u32(&ring[buf][arr][s][c]), src);
            }
        }
        if (tid < SBLK)
            CP_ASYNC4(smem_u32(&ring_b[buf][tid]), bp + (size_t)(t0 + tid) * NH);
        CP_COMMIT();
    };

    prefetch(0, 0);
    prefetch(1, 1);

    for (int blk = 0; blk < NBLK; blk++) {
        const int buf = blk & 1;
        CP_WAIT(1);
        __syncthreads();

#pragma unroll
        for (int s = 0; s < SBLK; s++) {
            const int t = blk * SBLK + s;
            const int P = t & 1;

            // load this thread's 16-wide q/k slices as packed pairs
            const ulonglong2* q64 = (const ulonglong2*)&ring[buf][0][s][pb];
            const ulonglong2* k64 = (const ulonglong2*)&ring[buf][1][s][pb];
            ull qa[8], ka[8];
#pragma unroll
            for (int j = 0; j < 4; j++) {
                ulonglong2 qq = q64[j], kk = k64[j];
                qa[2 * j] = qq.x; qa[2 * j + 1] = qq.y;
                ka[2 * j] = kk.x; ka[2 * j + 1] = kk.y;
            }
            const float kr = ring[buf][1][s][rc];
            const float vr = ring[buf][2][s][rc];
            const float beta = ring_b[buf][s];

            ull accO = 0ull, accR = 0ull;
#pragma unroll
            for (int j = 0; j < 8; j++) {
                FMA2(accO, qa[j], mcol2[j]);
                FMA2(accR, mrow2[j], ka[j]);
            }
            float oa, ob, ra, rb;
            upk2(accO, oa, ob);
            upk2(accR, ra, rb);
            float po = oa + ob, pr = ra + rb;
            po += __shfl_xor_sync(0xffffffffu, po, 1);
            po += __shfl_xor_sync(0xffffffffu, po, 2);
            pr += __shfl_xor_sync(0xffffffffu, pr, 1);
            pr += __shfl_xor_sync(0xffffffffu, pr, 2);

            const float bd = beta * (vr - pr);
            if (p == 0) {
                op[(size_t)t * DM + rc] = po;
                bd_sh[P][rc] = bd;
            }
            __syncthreads();

            const ull bdc2 = pk2(bd, bd);
            const ull kr2  = pk2(kr, kr);
            const ulonglong2* bd64 = (const ulonglong2*)&bd_sh[P][pb];
#pragma unroll
            for (int j = 0; j < 4; j++) {
                ulonglong2 bb = bd64[j];
                FMA2(mcol2[2 * j],     ka[2 * j],     bdc2);
                FMA2(mcol2[2 * j + 1], ka[2 * j + 1], bdc2);
                FMA2(mrow2[2 * j],     kr2, bb.x);
                FMA2(mrow2[2 * j + 1], kr2, bb.y);
            }
            // no trailing barrier: next step's bd uses opposite parity buffer
        }

        if (blk + 2 < NBLK) {
            prefetch(blk + 2, buf);   // safe: all ring[buf] reads precede step-7 barrier
        } else {
            CP_COMMIT();
        }
    }
}

// ---------------- RMSNorm fused with bf16 hi/lo split ----------------
__global__ __launch_bounds__(256)
void rms_split_kernel(const float* __restrict__ w,
                      __nv_bfloat16* __restrict__ hi, __nv_bfloat16* __restrict__ lo)
{
    int token = blockIdx.x;
    int tid = threadIdx.x;
    size_t off = (size_t)token * DM + tid * 4;
    float4 v = *(float4*)(g_att + off);
    float ss = v.x * v.x + v.y * v.y + v.z * v.z + v.w * v.w;
#pragma unroll
    for (int o = 16; o; o >>= 1) ss += __shfl_xor_sync(0xffffffffu, ss, o);
    __shared__ float sh[8];
    __shared__ float sscale;
    if ((tid & 31) == 0) sh[tid >> 5] = ss;
    __syncthreads();
    if (tid == 0) {
        float t = 0.f;
#pragma unroll
        for (int i = 0; i < 8; i++) t += sh[i];
        sscale = 1.f / sqrtf(t / (float)DM + 1e-6f);
    }
    __syncthreads();
    float s = sscale;
    float r0 = v.x * s * w[tid * 4 + 0];
    float r1 = v.y * s * w[tid * 4 + 1];
    float r2 = v.z * s * w[tid * 4 + 2];
    float r3 = v.w * s * w[tid * 4 + 3];

    __nv_bfloat16 h0 = __float2bfloat16(r0), h1 = __float2bfloat16(r1),
                  h2 = __float2bfloat16(r2), h3 = __float2bfloat16(r3);
    ((ushort4*)hi)[off / 4] = make_ushort4(__bfloat16_as_ushort(h0), __bfloat16_as_ushort(h1),
                                           __bfloat16_as_ushort(h2), __bfloat16_as_ushort(h3));
    __nv_bfloat16 l0 = __float2bfloat16(r0 - __bfloat162float(h0));
    __nv_bfloat16 l1 = __float2bfloat16(r1 - __bfloat162float(h1));
    __nv_bfloat16 l2 = __float2bfloat16(r2 - __bfloat162float(h2));
    __nv_bfloat16 l3 = __float2bfloat16(r3 - __bfloat162float(h3));
    ((ushort4*)lo)[off / 4] = make_ushort4(__bfloat16_as_ushort(l0), __bfloat16_as_ushort(l1),
                                           __bfloat16_as_ushort(l2), __bfloat16_as_ushort(l3));
}

// ---------------- launch ----------------
extern "C" void kernel_launch(void* const* d_in, const int* in_sizes, int n_in,
                              void* d_out, int out_size)
{
    const float* x    = (const float*)d_in[0];
    const float* Wq   = (const float*)d_in[1];
    const float* Wk   = (const float*)d_in[2];
    const float* Wv   = (const float*)d_in[3];
    const float* Wb   = (const float*)d_in[4];
    const float* Wo   = (const float*)d_in[5];
    const float* rmsw = (const float*)d_in[6];
    float* out = (float*)d_out;

    float *p_qraw, *p_kraw, *p_vraw, *p_att;
    __nv_bfloat16 *p_xhi, *p_xlo, *p_atthi, *p_attlo;
    __nv_bfloat16 *p_wqhi, *p_wqlo, *p_wkhi, *p_wklo, *p_wvhi, *p_wvlo, *p_wohi, *p_wolo;
    cudaGetSymbolAddress((void**)&p_qraw, g_qraw);
    cudaGetSymbolAddress((void**)&p_kraw, g_kraw);
    cudaGetSymbolAddress((void**)&p_vraw, g_vraw);
    cudaGetSymbolAddress((void**)&p_att,  g_att);
    cudaGetSymbolAddress((void**)&p_xhi,  g_xhi);
    cudaGetSymbolAddress((void**)&p_xlo,  g_xlo);
    cudaGetSymbolAddress((void**)&p_atthi, g_atthi);
    cudaGetSymbolAddress((void**)&p_attlo, g_attlo);
    cudaGetSymbolAddress((void**)&p_wqhi, g_wqhi);
    cudaGetSymbolAddress((void**)&p_wqlo, g_wqlo);
    cudaGetSymbolAddress((void**)&p_wkhi, g_wkhi);
    cudaGetSymbolAddress((void**)&p_wklo, g_wklo);
    cudaGetSymbolAddress((void**)&p_wvhi, g_wvhi);
    cudaGetSymbolAddress((void**)&p_wvlo, g_wvlo);
    cudaGetSymbolAddress((void**)&p_wohi, g_wohi);
    cudaGetSymbolAddress((void**)&p_wolo, g_wolo);

    cudaFuncSetAttribute(gemm_bs, cudaFuncAttributeMaxDynamicSharedMemorySize, GEMM_SMEM);

    const int n4x = TOKENS * DM / 4;
    const int n4w = DM * DM / 4;
    split_kernel<<<n4x / 256, 256>>>(x,  p_xhi,  p_xlo,  n4x);
    split_kernel<<<n4w / 256, 256>>>(Wq, p_wqhi, p_wqlo, n4w);
    split_kernel<<<n4w / 256, 256>>>(Wk, p_wkhi, p_wklo, n4w);
    split_kernel<<<n4w / 256, 256>>>(Wv, p_wvhi, p_wvlo, n4w);
    split_kernel<<<n4w / 256, 256>>>(Wo, p_wohi, p_wolo, n4w);

    dim3 gg(DM / 128, TOKENS / 128);
    gemm_bs<<<gg, 256, GEMM_SMEM>>>(p_xhi, p_xlo, p_wqhi, p_wqlo, p_qraw);
    gemm_bs<<<gg, 256, GEMM_SMEM>>>(p_xhi, p_xlo, p_wkhi, p_wklo, p_kraw);
    gemm_bs<<<gg, 256, GEMM_SMEM>>>(p_xhi, p_xlo, p_wvhi, p_wvlo, p_vraw);
    beta_kernel<<<TOKENS, 512>>>(x, Wb);
    act_kernel<<<TOKENS, 256>>>();
    scan_kernel<<<32, 256>>>();
    rms_split_kernel<<<TOKENS, 256>>>(rmsw, p_atthi, p_attlo);
    gemm_bs<<<gg, 256, GEMM_SMEM>>>(p_atthi, p_attlo, p_wohi, p_wolo, out);
}

// round 11
// speedup vs baseline: 1.4988x; 1.4988x over previous
#include <cuda_runtime.h>
#include <cuda_bf16.h>
#include <math.h>
#include <stdint.h>

#define TOKENS 2048
#define DM 1024
#define NH 16
#define HD 64

// ---------------- scratch (device globals: no allocs allowed) ----------------
__device__ float g_qraw[TOKENS * DM];
__device__ float g_kraw[TOKENS * DM];
__device__ float g_vraw[TOKENS * DM];
__device__ float g_beta[TOKENS * NH];
__device__ float g_att [TOKENS * DM];

__device__ __nv_bfloat16 g_xhi[TOKENS * DM], g_xlo[TOKENS * DM];
__device__ __nv_bfloat16 g_atthi[TOKENS * DM], g_attlo[TOKENS * DM];
__device__ __nv_bfloat16 g_wqhi[DM * DM], g_wqlo[DM * DM];
__device__ __nv_bfloat16 g_wkhi[DM * DM], g_wklo[DM * DM];
__device__ __nv_bfloat16 g_wvhi[DM * DM], g_wvlo[DM * DM];
__device__ __nv_bfloat16 g_wohi[DM * DM], g_wolo[DM * DM];

// ======================= helpers =======================
__device__ __forceinline__ uint32_t smem_u32(const void* p) {
    uint32_t a;
    asm("{ .reg .u64 t; cvta.to.shared.u64 t, %1; cvt.u32.u64 %0, t; }" : "=r"(a) : "l"(p));
    return a;
}
#define CP_ASYNC16(dst, src) \
    asm volatile("cp.async.cg.shared.global [%0], [%1], 16;" :: "r"(dst), "l"(src) : "memory")
#define CP_ASYNC4(dst, src) \
    asm volatile("cp.async.ca.shared.global [%0], [%1], 4;" :: "r"(dst), "l"(src) : "memory")
#define CP_COMMIT() asm volatile("cp.async.commit_group;" ::: "memory")
#define CP_WAIT(n)  asm volatile("cp.async.wait_group %0;" :: "n"(n) : "memory")
#define SWZ(off) ((off) ^ (((off) >> 3) & 0x70))

__device__ __forceinline__ void ldm4(uint32_t addr, uint32_t* r) {
    asm volatile("ldmatrix.sync.aligned.m8n8.x4.shared.b16 {%0,%1,%2,%3}, [%4];"
                 : "=r"(r[0]), "=r"(r[1]), "=r"(r[2]), "=r"(r[3]) : "r"(addr));
}
__device__ __forceinline__ void mma16816(float* c, const uint32_t* a, const uint32_t* b) {
    asm volatile(
        "mma.sync.aligned.m16n8k16.row.col.f32.bf16.bf16.f32 "
        "{%0,%1,%2,%3}, {%4,%5,%6,%7}, {%8,%9}, {%0,%1,%2,%3};"
        : "+f"(c[0]), "+f"(c[1]), "+f"(c[2]), "+f"(c[3])
        : "r"(a[0]), "r"(a[1]), "r"(a[2]), "r"(a[3]), "r"(b[0]), "r"(b[1]));
}

// ---------------- batched fp32 -> bf16 hi/lo split (x + 4 weights) ----------------
__device__ __forceinline__ void split_one(const float* __restrict__ src,
                                          __nv_bfloat16* __restrict__ hi,
                                          __nv_bfloat16* __restrict__ lo, int i)
{
    float4 v = ((const float4*)src)[i];
    __nv_bfloat16 hx = __float2bfloat16(v.x), hy = __float2bfloat16(v.y),
                  hz = __float2bfloat16(v.z), hw = __float2bfloat16(v.w);
    ((ushort4*)hi)[i] = make_ushort4(__bfloat16_as_ushort(hx), __bfloat16_as_ushort(hy),
                                     __bfloat16_as_ushort(hz), __bfloat16_as_ushort(hw));
    __nv_bfloat16 lx = __float2bfloat16(v.x - __bfloat162float(hx));
    __nv_bfloat16 ly = __float2bfloat16(v.y - __bfloat162float(hy));
    __nv_bfloat16 lz = __float2bfloat16(v.z - __bfloat162float(hz));
    __nv_bfloat16 lw = __float2bfloat16(v.w - __bfloat162float(hw));
    ((ushort4*)lo)[i] = make_ushort4(__bfloat16_as_ushort(lx), __bfloat16_as_ushort(ly),
                                     __bfloat16_as_ushort(lz), __bfloat16_as_ushort(lw));
}

#define NX4 (TOKENS * DM / 4)   // 524288
#define NW4 (DM * DM / 4)       // 262144

__global__ __launch_bounds__(256)
void split5_kernel(const float* __restrict__ x,  const float* __restrict__ Wq,
                   const float* __restrict__ Wk, const float* __restrict__ Wv,
                   const float* __restrict__ Wo)
{
    int i = blockIdx.x * 256 + threadIdx.x;
    if (i < NX4) {
        split_one(x, g_xhi, g_xlo, i);
    } else {
        int r = i - NX4;
        int w = r >> 18;          // / NW4
        int j = r & (NW4 - 1);
        switch (w) {
            case 0: split_one(Wq, g_wqhi, g_wqlo, j); break;
            case 1: split_one(Wk, g_wkhi, g_wklo, j); break;
            case 2: split_one(Wv, g_wvhi, g_wvlo, j); break;
            default: split_one(Wo, g_wohi, g_wolo, j); break;
        }
    }
}

// =================== tensor-core GEMM body: C[2048,1024] = A * B^T ===================
#define STAGE_BYTES 65536
#define GEMM_SMEM (2 * STAGE_BYTES)

__device__ __forceinline__ void stage_load(
    uint32_t sb, int stage, int tid, int m0, int n0, int k0,
    const __nv_bfloat16* __restrict__ Ahi, const __nv_bfloat16* __restrict__ Alo,
    const __nv_bfloat16* __restrict__ Bhi, const __nv_bfloat16* __restrict__ Blo)
{
#pragma unroll
    for (int i = 0; i < 16; i++) {
        const int mi = i >> 2;
        const int cid = ((i & 3) << 8) + tid;
        const int row = cid >> 3;
        const int c16 = cid & 7;
        const __nv_bfloat16* g = (mi == 0) ? Ahi : (mi == 1) ? Alo : (mi == 2) ? Bhi : Blo;
        const int grow = ((mi < 2) ? m0 : n0) + row;
        const void* src = g + (size_t)grow * DM + k0 + c16 * 8;
        uint32_t off = (uint32_t)(row * 128 + c16 * 16);
        uint32_t dst = sb + stage * STAGE_BYTES + mi * 16384 + SWZ(off);
        CP_ASYNC16(dst, src);
    }
    CP_COMMIT();
}

__device__ __forceinline__ void gemm_body(
    char* smem,
    const __nv_bfloat16* __restrict__ Ahi, const __nv_bfloat16* __restrict__ Alo,
    const __nv_bfloat16* __restrict__ Bhi, const __nv_bfloat16* __restrict__ Blo,
    float* __restrict__ C)
{
    const uint32_t sb = smem_u32(smem);
    const int tid = threadIdx.x;
    const int wid = tid >> 5;
    const int lane = tid & 31;
    const int m0 = blockIdx.y * 128;
    const int n0 = blockIdx.x * 128;
    const int wm = (wid & 3) * 32;
    const int wn = (wid >> 2) * 64;

    float acc[2][8][4];
#pragma unroll
    for (int mt = 0; mt < 2; mt++)
#pragma unroll
        for (int nt = 0; nt < 8; nt++)
#pragma unroll
            for (int j = 0; j < 4; j++) acc[mt][nt][j] = 0.f;

    stage_load(sb, 0, tid, m0, n0, 0, Ahi, Alo, Bhi, Blo);

    for (int ch = 0; ch < 16; ch++) {
        if (ch < 15) {
            stage_load(sb, (ch + 1) & 1, tid, m0, n0, (ch + 1) * 64, Ahi, Alo, Bhi, Blo);
            CP_WAIT(1);
        } else {
            CP_WAIT(0);
        }
        __syncthreads();

        const uint32_t sA_hi = sb + (ch & 1) * STAGE_BYTES;
        const uint32_t sA_lo = sA_hi + 16384;
        const uint32_t sB_hi = sA_hi + 32768;
        const uint32_t sB_lo = sA_hi + 49152;

#pragma unroll
        for (int kk = 0; kk < 4; kk++) {
            const int kb = kk * 32 + ((lane >> 4) & 1) * 16;

            uint32_t ahi[2][4], alo[2][4];
#pragma unroll
            for (int mt = 0; mt < 2; mt++) {
                uint32_t off = (uint32_t)((wm + mt * 16 + (lane & 15)) * 128 + kb);
                uint32_t so = SWZ(off);
                ldm4(sA_hi + so, ahi[mt]);
                ldm4(sA_lo + so, alo[mt]);
            }

            uint32_t bhi[8][2], blo[8][2];
#pragma unroll
            for (int p = 0; p < 4; p++) {
                uint32_t off = (uint32_t)((wn + p * 16 + (lane & 15)) * 128 + kb);
                uint32_t so = SWZ(off);
                uint32_t t[4];
                ldm4(sB_hi + so, t);
                bhi[2 * p][0] = t[0]; bhi[2 * p + 1][0] = t[1];
                bhi[2 * p][1] = t[2]; bhi[2 * p + 1][1] = t[3];
                ldm4(sB_lo + so, t);
                blo[2 * p][0] = t[0]; blo[2 * p + 1][0] = t[1];
                blo[2 * p][1] = t[2]; blo[2 * p + 1][1] = t[3];
            }

#pragma unroll
            for (int mt = 0; mt < 2; mt++)
#pragma unroll
                for (int nt = 0; nt < 8; nt++) {
                    mma16816(acc[mt][nt], ahi[mt], bhi[nt]);
                    mma16816(acc[mt][nt], ahi[mt], blo[nt]);
                    mma16816(acc[mt][nt], alo[mt], bhi[nt]);
                }
        }
        __syncthreads();
    }

#pragma unroll
    for (int mt = 0; mt < 2; mt++) {
        const int r0 = m0 + wm + mt * 16 + (lane >> 2);
#pragma unroll
        for (int nt = 0; nt < 8; nt++) {
            const int c0 = n0 + wn + nt * 8 + 2 * (lane & 3);
            *(float2*)(C + (size_t)r0 * DM + c0)       = make_float2(acc[mt][nt][0], acc[mt][nt][1]);
            *(float2*)(C + (size_t)(r0 + 8) * DM + c0) = make_float2(acc[mt][nt][2], acc[mt][nt][3]);
        }
    }
}

// fused QKV: z selects weight/output
__global__ __launch_bounds__(256, 1)
void gemm_qkv()
{
    extern __shared__ char smem[];
    const __nv_bfloat16 *Bhi, *Blo;
    float* C;
    if (blockIdx.z == 0)      { Bhi = g_wqhi; Blo = g_wqlo; C = g_qraw; }
    else if (blockIdx.z == 1) { Bhi = g_wkhi; Blo = g_wklo; C = g_kraw; }
    else                      { Bhi = g_wvhi; Blo = g_wvlo; C = g_vraw; }
    gemm_body(smem, g_xhi, g_xlo, Bhi, Blo, C);
}

__global__ __launch_bounds__(256, 1)
void gemm_wo(float* __restrict__ C)
{
    extern __shared__ char smem[];
    gemm_body(smem, g_atthi, g_attlo, g_wohi, g_wolo, C);
}

// ---------------- beta = 2*sigmoid(x @ Wb^T), one warp per head ----------------
__global__ __launch_bounds__(512)
void beta_kernel(const float* __restrict__ x, const float* __restrict__ Wb)
{
    int token = blockIdx.x;
    int w = threadIdx.x >> 5;
    int lane = threadIdx.x & 31;
    const float* xr = x + (size_t)token * DM;
    const float* wr = Wb + (size_t)w * DM;
    float s = 0.f;
    for (int j = lane; j < DM; j += 32) s += xr[j] * wr[j];
#pragma unroll
    for (int o = 16; o; o >>= 1) s += __shfl_xor_sync(0xffffffffu, s, o);
    if (lane == 0) g_beta[token * NH + w] = 2.f / (1.f + __expf(-s));
}

__device__ __forceinline__ float silu(float v) { return v / (1.f + __expf(-v)); }

// ------- silu + per-head L2 normalize for q,k; silu for v (in place) -------
__global__ __launch_bounds__(256)
void act_kernel()
{
    int token = blockIdx.x;
    int tid = threadIdx.x;
    size_t off = (size_t)token * DM + tid * 4;

    float4 q = *(float4*)(g_qraw + off);
    q.x = silu(q.x); q.y = silu(q.y); q.z = silu(q.z); q.w = silu(q.w);
    float ss = q.x * q.x + q.y * q.y + q.z * q.z + q.w * q.w;
#pragma unroll
    for (int o = 8; o; o >>= 1) ss += __shfl_xor_sync(0xffffffffu, ss, o);
    float inv = 1.f / (sqrtf(ss) + 1e-6f);
    q.x *= inv; q.y *= inv; q.z *= inv; q.w *= inv;
    *(float4*)(g_qraw + off) = q;

    float4 k = *(float4*)(g_kraw + off);
    k.x = silu(k.x); k.y = silu(k.y); k.z = silu(k.z); k.w = silu(k.w);
    float sk = k.x * k.x + k.y * k.y + k.z * k.z + k.w * k.w;
#pragma unroll
    for (int o = 8; o; o >>= 1) sk += __shfl_xor_sync(0xffffffffu, sk, o);
    float invk = 1.f / (sqrtf(sk) + 1e-6f);
    k.x *= invk; k.y *= invk; k.z *= invk; k.w *= invk;
    *(float4*)(g_kraw + off) = k;

    float4 v = *(float4*)(g_vraw + off);
    v.x = silu(v.x); v.y = silu(v.y); v.z = silu(v.z); v.w = silu(v.w);
    *(float4*)(g_vraw + off) = v;
}

// ---------------- sequential delta-rule scan: R5 structure, 512 threads ----------------
// Thread (qr, lane64): qr = tid>>6 (0..7), lane64 = tid&63.
//   mcol[i] = M[qr*8+i][c]  (c = lane64) -> out = M^T q, col update
//   mrow[i] = M[r][qr*8+i]  (r = lane64) -> retrieved = M k, row update
// 8-way partial reduction through smem; 2 barriers/step (parity-buffered).
#define SBLK 8
#define NBLK (1024 / SBLK)

__global__ __launch_bounds__(512, 1)
void scan_kernel()
{
    const int pair = blockIdx.x;
    const int b = pair >> 4, h = pair & 15;
    const int tid = threadIdx.x;
    const int lane64 = tid & 63;
    const int qr = tid >> 6;          // 0..7
    const int base = qr * 8;

    __shared__ float ring[2][3][SBLK][64];
    __shared__ float ring_b[2][SBLK];
    __shared__ float partR[2][8][64], partO[2][8][64];
    __shared__ float bd_sh[2][64];

    float mcol[8], mrow[8];
#pragma unroll
    for (int i = 0; i < 8; i++) { mcol[i] = 0.f; mrow[i] = 0.f; }

    const size_t hb = (size_t)b * 1024 * DM + h * HD;
    const float* qp = g_qraw + hb;
    const float* kp = g_kraw + hb;
    const float* vp = g_vraw + hb;
    const float* bp = g_beta + (size_t)b * 1024 * NH + h;
    float* op = g_att + hb;

    auto prefetch = [&](int blk, int buf) {
        const int t0 = blk * SBLK;
        if (tid < 384) {
            int arr = tid >> 7;             // 0=q 1=k 2=v
            int rem = tid & 127;
            int s = rem >> 4;
            int c = (rem & 15) * 4;
            const float* src = (arr == 0 ? qp : arr == 1 ? kp : vp)
                               + (size_t)(t0 + s) * DM + c;
            CP_ASYNC16(smem_u32(&ring[buf][arr][s][c]), src);
        }
        if (tid < SBLK)
            CP_ASYNC4(smem_u32(&ring_b[buf][tid]), bp + (size_t)(t0 + tid) * NH);
        CP_COMMIT();
    };

    prefetch(0, 0);
    prefetch(1, 1);

    for (int blk = 0; blk < NBLK; blk++) {
        const int buf = blk & 1;
        CP_WAIT(1);
        __syncthreads();

#pragma unroll
        for (int s = 0; s < SBLK; s++) {
            const int t = blk * SBLK + s;
            const int p = t & 1;
            const float* q_sh = ring[buf][0][s];
            const float* k_sh = ring[buf][1][s];
            const float* v_sh = ring[buf][2][s];

            float kreg[8];
#pragma unroll
            for (int i = 0; i < 8; i++) kreg[i] = k_sh[base + i];

            float pr0 = 0.f, pr1 = 0.f, po0 = 0.f, po1 = 0.f;
#pragma unroll
            for (int i = 0; i < 8; i += 2) {
                pr0 += mrow[i]     * kreg[i];
                pr1 += mrow[i + 1] * kreg[i + 1];
                po0 += q_sh[base + i]     * mcol[i];
                po1 += q_sh[base + i + 1] * mcol[i + 1];
            }
            partR[p][qr][lane64] = pr0 + pr1;
            partO[p][qr][lane64] = po0 + po1;
            __syncthreads();

            if (tid < 64) {
                float rs = (partR[p][0][tid] + partR[p][1][tid])
                         + (partR[p][2][tid] + partR[p][3][tid])
                         + (partR[p][4][tid] + partR[p][5][tid])
                         + (partR[p][6][tid] + partR[p][7][tid]);
                bd_sh[p][tid] = ring_b[buf][s] * (v_sh[tid] - rs);
            } else if (tid < 128) {
                int c = tid - 64;
                float os = (partO[p][0][c] + partO[p][1][c])
                         + (partO[p][2][c] + partO[p][3][c])
                         + (partO[p][4][c] + partO[p][5][c])
                         + (partO[p][6][c] + partO[p][7][c]);
                op[(size_t)t * DM + c] = os;
            }
            __syncthreads();

            const float bdc = bd_sh[p][lane64];
            const float kr  = k_sh[lane64];
#pragma unroll
            for (int i = 0; i < 8; i++) {
                mcol[i] += kreg[i] * bdc;
                mrow[i] += kr * bd_sh[p][base + i];
            }
            // no trailing barrier: next step uses opposite-parity buffers
        }

        if (blk + 2 < NBLK) {
            __syncthreads();
            prefetch(blk + 2, buf);
        } else {
            CP_COMMIT();
        }
    }
}

// ---------------- RMSNorm fused with bf16 hi/lo split ----------------
__global__ __launch_bounds__(256)
void rms_split_kernel(const float* __restrict__ w)
{
    int token = blockIdx.x;
    int tid = threadIdx.x;
    size_t off = (size_t)token * DM + tid * 4;
    float4 v = *(float4*)(g_att + off);
    float ss = v.x * v.x + v.y * v.y + v.z * v.z + v.w * v.w;
#pragma unroll
    for (int o = 16; o; o >>= 1) ss += __shfl_xor_sync(0xffffffffu, ss, o);
    __shared__ float sh[8];
    __shared__ float sscale;
    if ((tid & 31) == 0) sh[tid >> 5] = ss;
    __syncthreads();
    if (tid == 0) {
        float t = 0.f;
#pragma unroll
        for (int i = 0; i < 8; i++) t += sh[i];
        sscale = 1.f / sqrtf(t / (float)DM + 1e-6f);
    }
    __syncthreads();
    float s = sscale;
    float r0 = v.x * s * w[tid * 4 + 0];
    float r1 = v.y * s * w[tid * 4 + 1];
    float r2 = v.z * s * w[tid * 4 + 2];
    float r3 = v.w * s * w[tid * 4 + 3];

    __nv_bfloat16 h0 = __float2bfloat16(r0), h1 = __float2bfloat16(r1),
                  h2 = __float2bfloat16(r2), h3 = __float2bfloat16(r3);
    ((ushort4*)g_atthi)[off / 4] = make_ushort4(__bfloat16_as_ushort(h0), __bfloat16_as_ushort(h1),
                                                __bfloat16_as_ushort(h2), __bfloat16_as_ushort(h3));
    __nv_bfloat16 l0 = __float2bfloat16(r0 - __bfloat162float(h0));
    __nv_bfloat16 l1 = __float2bfloat16(r1 - __bfloat162float(h1));
    __nv_bfloat16 l2 = __float2bfloat16(r2 - __bfloat162float(h2));
    __nv_bfloat16 l3 = __float2bfloat16(r3 - __bfloat162float(h3));
    ((ushort4*)g_attlo)[off / 4] = make_ushort4(__bfloat16_as_ushort(l0), __bfloat16_as_ushort(l1),
                                                __bfloat16_as_ushort(l2), __bfloat16_as_ushort(l3));
}

// ---------------- launch ----------------
extern "C" void kernel_launch(void* const* d_in, const int* in_sizes, int n_in,
                              void* d_out, int out_size)
{
    const float* x    = (const float*)d_in[0];
    const float* Wq   = (const float*)d_in[1];
    const float* Wk   = (const float*)d_in[2];
    const float* Wv   = (const float*)d_in[3];
    const float* Wb   = (const float*)d_in[4];
    const float* Wo   = (const float*)d_in[5];
    const float* rmsw = (const float*)d_in[6];
    float* out = (float*)d_out;

    cudaFuncSetAttribute(gemm_qkv, cudaFuncAttributeMaxDynamicSharedMemorySize, GEMM_SMEM);
    cudaFuncSetAttribute(gemm_wo,  cudaFuncAttributeMaxDynamicSharedMemorySize, GEMM_SMEM);

    const int nsplit = NX4 + 4 * NW4;              // 1572864 float4 slots
    split5_kernel<<<nsplit / 256, 256>>>(x, Wq, Wk, Wv, Wo);

    dim3 gq(DM / 128, TOKENS / 128, 3);            // (8,16,3) = 384 CTAs
    gemm_qkv<<<gq, 256, GEMM_SMEM>>>();
    beta_kernel<<<TOKENS, 512>>>(x, Wb);
    act_kernel<<<TOKENS, 256>>>();
    scan_kernel<<<32, 512>>>();
    rms_split_kernel<<<TOKENS, 256>>>(rmsw);
    dim3 gg(DM / 128, TOKENS / 128);
    gemm_wo<<<gg, 256, GEMM_SMEM>>>(out);
}